// round 4
// baseline (speedup 1.0000x reference)
#include <cuda_runtime.h>
#include <cstdint>

// Problem constants (fixed by the dataset)
#define NN 50000
#define EE 800000
#define FIN 128
#define FH 96
#define FOUT 64
#define BN_EPS 1e-5f

// ----------------------------------------------------------------------------
// Device scratch (static allocation — no cudaMalloc allowed).
// Referenced ONLY from device code.
// ----------------------------------------------------------------------------
__device__ float g_deg[NN];
__device__ float g_dis[NN];
__device__ int   g_cnt[NN];
__device__ int   g_cursor[NN];
__device__ int   g_excl[NN];
__device__ int   g_bsums[64];
__device__ int   g_rowptr[NN + 1];
__device__ int   g_src[EE];
__device__ float g_norm[EE];
__device__ float g_xw[(size_t)NN * FH];   // GEMM output buffer (max F = 96)
__device__ float g_h[(size_t)NN * FH];    // layer activation buffer
__device__ float g_sc[3][FH];
__device__ float g_sh[3][FH];

// ----------------------------------------------------------------------------
// Graph-norm build.  edge_index is int32 (JAX silently downcasts int64
// without x64 enabled): row = ei[e], col = ei[EE + e].
// ----------------------------------------------------------------------------
__global__ void zero_init() {
    int i = blockIdx.x * blockDim.x + threadIdx.x;
    if (i < NN) { g_deg[i] = 0.f; g_cnt[i] = 0; g_cursor[i] = 0; }
}

__global__ void deg_count(const int* __restrict__ ei, const float* __restrict__ ew) {
    int e = blockIdx.x * blockDim.x + threadIdx.x;
    if (e >= EE) return;
    int c = ei[EE + e];
    atomicAdd(&g_deg[c], ew[e]);
    atomicAdd(&g_cnt[c], 1);
}

__global__ void compute_dis() {
    int i = blockIdx.x * blockDim.x + threadIdx.x;
    if (i < NN) g_dis[i] = rsqrtf(g_deg[i] + 1.0f);  // +1 = self-loop weight; always > 0
}

// Exclusive scan of g_cnt into g_rowptr (3 phases)
__global__ void scan_block() {
    __shared__ int sh[1024];
    int tid = threadIdx.x;
    int i = blockIdx.x * 1024 + tid;
    int v = (i < NN) ? g_cnt[i] : 0;
    sh[tid] = v;
    __syncthreads();
    for (int off = 1; off < 1024; off <<= 1) {
        int t = (tid >= off) ? sh[tid - off] : 0;
        __syncthreads();
        sh[tid] += t;
        __syncthreads();
    }
    if (i < NN) g_excl[i] = sh[tid] - v;      // exclusive within block
    if (tid == 1023) g_bsums[blockIdx.x] = sh[1023];
}

__global__ void scan_sums(int nb) {
    if (threadIdx.x == 0) {
        int acc = 0;
        for (int b = 0; b < nb; ++b) { int t = g_bsums[b]; g_bsums[b] = acc; acc += t; }
    }
}

__global__ void scan_add() {
    int i = blockIdx.x * 1024 + threadIdx.x;
    if (i < NN) g_rowptr[i] = g_excl[i] + g_bsums[blockIdx.x];
    if (blockIdx.x == 0 && threadIdx.x == 0) g_rowptr[NN] = EE;
}

__global__ void fill_csr(const int* __restrict__ ei, const float* __restrict__ ew) {
    int e = blockIdx.x * blockDim.x + threadIdx.x;
    if (e >= EE) return;
    int r = ei[e];
    int c = ei[EE + e];
    float nrm = g_dis[r] * ew[e] * g_dis[c];
    int pos = g_rowptr[c] + atomicAdd(&g_cursor[c], 1);
    g_src[pos] = r;
    g_norm[pos] = nrm;
}

// ----------------------------------------------------------------------------
// BN(eval) + bias folding:  y = (agg + b - m) * g*rsqrt(v+eps) + beta
//                             = agg * sc + sh        (stored in g_sc[layer])
// ----------------------------------------------------------------------------
__global__ void bn_affine(const float* __restrict__ g, const float* __restrict__ beta,
                          const float* __restrict__ m, const float* __restrict__ v,
                          const float* __restrict__ b, int layer, int F) {
    int f = threadIdx.x;
    if (f < F) {
        float a = g[f] * rsqrtf(v[f] + BN_EPS);
        g_sc[layer][f] = a;
        g_sh[layer][f] = (b[f] - m[f]) * a + beta[f];
    }
}

__global__ void affine_identity(const float* __restrict__ b, int layer, int F) {
    int f = threadIdx.x;
    if (f < F) { g_sc[layer][f] = 1.0f; g_sh[layer][f] = b[f]; }
}

// ----------------------------------------------------------------------------
// Register-blocked SIMT GEMM:  g_xw[i,f] = sum_k X[i,k] * W[f,k]
//   FROM_H=true: input is the internal activation buffer g_h.
// ----------------------------------------------------------------------------
template <int KDIM, int BN, int TN, bool FROM_H>
__global__ void gemm_xwT(const float* __restrict__ Xext, const float* __restrict__ W) {
    constexpr int BM = 64, BK = 16, TM = 4;
    constexpr int CT = BN / TN;
    constexpr int RT = BM / TM;   // CT*RT = 256 threads
    const float* __restrict__ X = FROM_H ? (const float*)g_h : Xext;
    float* __restrict__ Y = g_xw;
    __shared__ float xs[BK][BM + 4];
    __shared__ float ws[BK][BN + 4];
    int tid = threadIdx.x;
    int tx = tid % CT, ty = tid / CT;
    int row0 = blockIdx.x * BM;
    float acc[TM][TN] = {};
    for (int k0 = 0; k0 < KDIM; k0 += BK) {
#pragma unroll
        for (int l = 0; l < (BM * BK) / (CT * RT); ++l) {
            int idx = tid + l * CT * RT;
            int m = idx / BK, kk = idx % BK;
            int r = row0 + m;
            xs[kk][m] = (r < NN) ? X[(size_t)r * KDIM + k0 + kk] : 0.f;
        }
#pragma unroll
        for (int l = 0; l < (BN * BK + CT * RT - 1) / (CT * RT); ++l) {
            int idx = tid + l * CT * RT;
            if (idx < BN * BK) {
                int f = idx / BK, kk = idx % BK;
                ws[kk][f] = W[(size_t)f * KDIM + k0 + kk];
            }
        }
        __syncthreads();
#pragma unroll
        for (int kk = 0; kk < BK; ++kk) {
            float a[TM], b[TN];
#pragma unroll
            for (int m = 0; m < TM; ++m) a[m] = xs[kk][ty * TM + m];
#pragma unroll
            for (int n = 0; n < TN; ++n) b[n] = ws[kk][tx * TN + n];
#pragma unroll
            for (int m = 0; m < TM; ++m)
#pragma unroll
                for (int n = 0; n < TN; ++n) acc[m][n] += a[m] * b[n];
        }
        __syncthreads();
    }
#pragma unroll
    for (int m = 0; m < TM; ++m) {
        int r = row0 + ty * TM + m;
        if (r < NN) {
#pragma unroll
            for (int n = 0; n < TN; ++n)
                Y[(size_t)r * BN + tx * TN + n] = acc[m][n];
        }
    }
}

// ----------------------------------------------------------------------------
// CSR aggregation, one warp per destination node, F features in registers.
//   out[i,f] = act( (sum_e norm_e*g_xw[src_e,f] + dis[i]^2*g_xw[i,f]) * sc + sh )
//   TO_H=true: write internal buffer g_h; else write external out pointer.
// ----------------------------------------------------------------------------
template <int F, bool RELU, bool TO_H, int LAYER>
__global__ void aggregate(float* __restrict__ outExt) {
    int warp = blockIdx.x * (blockDim.x >> 5) + (threadIdx.x >> 5);
    if (warp >= NN) return;
    int lane = threadIdx.x & 31;
    const float* __restrict__ xw = g_xw;
    float* __restrict__ out = TO_H ? (float*)g_h : outExt;
    constexpr int FPL = F / 32;
    float acc[FPL];
#pragma unroll
    for (int k = 0; k < FPL; ++k) acc[k] = 0.f;

    int s = g_rowptr[warp], t = g_rowptr[warp + 1];
    for (int base = s; base < t; base += 32) {
        int idx = base + lane;
        int src = 0; float nrm = 0.f;
        if (idx < t) { src = g_src[idx]; nrm = g_norm[idx]; }
        int cnt = min(32, t - base);
        for (int j = 0; j < cnt; ++j) {
            int ssrc = __shfl_sync(0xffffffffu, src, j);
            float snrm = __shfl_sync(0xffffffffu, nrm, j);
            const float* p = xw + (size_t)ssrc * F + lane;
#pragma unroll
            for (int k = 0; k < FPL; ++k) acc[k] += snrm * p[k * 32];
        }
    }
    // self loop: norm = dis[i] * 1.0 * dis[i]
    float d = g_dis[warp];
    float sn = d * d;
    const float* p = xw + (size_t)warp * F + lane;
#pragma unroll
    for (int k = 0; k < FPL; ++k) acc[k] += sn * p[k * 32];

#pragma unroll
    for (int k = 0; k < FPL; ++k) {
        int f = lane + 32 * k;
        float v = acc[k] * g_sc[LAYER][f] + g_sh[LAYER][f];
        if (RELU) v = fmaxf(v, 0.f);
        out[(size_t)warp * F + f] = v;
    }
}

// ----------------------------------------------------------------------------
// Launch — kernel launches ONLY (graph-capturable)
// ----------------------------------------------------------------------------
extern "C" void kernel_launch(void* const* d_in, const int* in_sizes, int n_in,
                              void* d_out, int out_size) {
    const float* x   = (const float*)d_in[0];
    const int*   ei  = (const int*)d_in[1];       // int32! (JAX x64 disabled)
    const float* ew  = (const float*)d_in[2];
    const float* W1  = (const float*)d_in[3];
    const float* b1  = (const float*)d_in[4];
    const float* W2  = (const float*)d_in[5];
    const float* b2  = (const float*)d_in[6];
    const float* W3  = (const float*)d_in[7];
    const float* b3  = (const float*)d_in[8];
    const float* g1  = (const float*)d_in[9];
    const float* be1 = (const float*)d_in[10];
    const float* m1  = (const float*)d_in[11];
    const float* v1  = (const float*)d_in[12];
    const float* g2  = (const float*)d_in[13];
    const float* be2 = (const float*)d_in[14];
    const float* m2  = (const float*)d_in[15];
    const float* v2  = (const float*)d_in[16];
    float* out = (float*)d_out;

    const int nbN    = (NN + 255) / 256;
    const int nbE    = (EE + 255) / 256;
    const int nbScan = (NN + 1023) / 1024;   // 49

    // Graph norm + CSR build
    zero_init<<<nbN, 256>>>();
    deg_count<<<nbE, 256>>>(ei, ew);
    compute_dis<<<nbN, 256>>>();
    scan_block<<<nbScan, 1024>>>();
    scan_sums<<<1, 32>>>(nbScan);
    scan_add<<<nbScan, 1024>>>();
    fill_csr<<<nbE, 256>>>(ei, ew);

    // Folded affine params
    bn_affine<<<1, FH>>>(g1, be1, m1, v1, b1, 0, FH);
    bn_affine<<<1, FH>>>(g2, be2, m2, v2, b2, 1, FH);
    affine_identity<<<1, FOUT>>>(b3, 2, FOUT);

    const int gemmBlocks = (NN + 63) / 64;
    const int aggBlocks  = (NN + 7) / 8;     // 8 warps/block of 256 threads

    // Layer 1: xw = x @ W1^T ; h = relu(bn(agg(xw)))
    gemm_xwT<FIN, FH, 6, false><<<gemmBlocks, 256>>>(x, W1);
    aggregate<FH, true, true, 0><<<aggBlocks, 256>>>(nullptr);

    // Layer 2
    gemm_xwT<FH, FH, 6, true><<<gemmBlocks, 256>>>(nullptr, W2);
    aggregate<FH, true, true, 1><<<aggBlocks, 256>>>(nullptr);

    // Layer 3: out = agg(h @ W3^T) + b3
    gemm_xwT<FH, FOUT, 4, true><<<gemmBlocks, 256>>>(nullptr, W3);
    aggregate<FOUT, false, false, 2><<<aggBlocks, 256>>>(out);
}

// round 5
// speedup vs baseline: 1.0386x; 1.0386x over previous
#include <cuda_runtime.h>
#include <cstdint>

#define NN 50000
#define EE 800000
#define FIN 128
#define FH 96
#define FOUT 64
#define BN_EPS 1e-5f

// ----------------------------------------------------------------------------
// Device scratch (static; no cudaMalloc anywhere)
// ----------------------------------------------------------------------------
__device__ float g_deg[NN];
__device__ float g_dis[NN];
__device__ int   g_cnt[NN];
__device__ int   g_cursor[NN];
__device__ int   g_excl[NN];
__device__ int   g_bsums[64];
__device__ int   g_rowptr[NN + 1];
__device__ int   g_src[EE];
__device__ float g_norm[EE];
__device__ float g_xw[(size_t)NN * FH];
__device__ float g_h[(size_t)NN * FH];
__device__ float g_sc[3][FH];
__device__ float g_sh[3][FH];

// ----------------------------------------------------------------------------
// Graph-norm + CSR build (edge_index is int32; col = ei[EE + e])
// ----------------------------------------------------------------------------
__global__ void zero_init() {
    int i = blockIdx.x * blockDim.x + threadIdx.x;
    if (i < NN) { g_deg[i] = 0.f; g_cnt[i] = 0; g_cursor[i] = 0; }
}

__global__ void deg_count(const int* __restrict__ ei, const float* __restrict__ ew) {
    int e = blockIdx.x * blockDim.x + threadIdx.x;
    if (e >= EE) return;
    int c = ei[EE + e];
    atomicAdd(&g_deg[c], ew[e]);
    atomicAdd(&g_cnt[c], 1);
}

// Block-level exclusive scan of g_cnt; also computes g_dis (independent work).
__global__ void scan_block() {
    __shared__ int sh[1024];
    int tid = threadIdx.x;
    int i = blockIdx.x * 1024 + tid;
    int v = (i < NN) ? g_cnt[i] : 0;
    if (i < NN) g_dis[i] = rsqrtf(g_deg[i] + 1.0f);   // self-loop weight 1 => deg>0
    sh[tid] = v;
    __syncthreads();
    for (int off = 1; off < 1024; off <<= 1) {
        int t = (tid >= off) ? sh[tid - off] : 0;
        __syncthreads();
        sh[tid] += t;
        __syncthreads();
    }
    if (i < NN) g_excl[i] = sh[tid] - v;
    if (tid == 1023) g_bsums[blockIdx.x] = sh[1023];
}

__global__ void scan_sums(int nb) {
    if (threadIdx.x == 0) {
        int acc = 0;
        for (int b = 0; b < nb; ++b) { int t = g_bsums[b]; g_bsums[b] = acc; acc += t; }
    }
}

__global__ void scan_add() {
    int i = blockIdx.x * 1024 + threadIdx.x;
    if (i < NN) g_rowptr[i] = g_excl[i] + g_bsums[blockIdx.x];
    if (blockIdx.x == 0 && threadIdx.x == 0) g_rowptr[NN] = EE;
}

__global__ void fill_csr(const int* __restrict__ ei, const float* __restrict__ ew) {
    int e = blockIdx.x * blockDim.x + threadIdx.x;
    if (e >= EE) return;
    int r = ei[e];
    int c = ei[EE + e];
    float nrm = g_dis[r] * ew[e] * g_dis[c];
    int pos = g_rowptr[c] + atomicAdd(&g_cursor[c], 1);
    g_src[pos] = r;
    g_norm[pos] = nrm;
}

// ----------------------------------------------------------------------------
// Folded affine for all 3 layers in one launch. blockIdx.x = layer.
//   layers 0,1: y = agg*sc + sh  with sc=g*rsqrt(v+eps), sh=(b-m)*sc+beta
//   layer  2:   sc=1, sh=b3
// ----------------------------------------------------------------------------
__global__ void affine_all(const float* g1, const float* be1, const float* m1, const float* v1, const float* b1,
                           const float* g2, const float* be2, const float* m2, const float* v2, const float* b2,
                           const float* b3) {
    int f = threadIdx.x;
    int L = blockIdx.x;
    if (L == 0 && f < FH) {
        float a = g1[f] * rsqrtf(v1[f] + BN_EPS);
        g_sc[0][f] = a;
        g_sh[0][f] = (b1[f] - m1[f]) * a + be1[f];
    } else if (L == 1 && f < FH) {
        float a = g2[f] * rsqrtf(v2[f] + BN_EPS);
        g_sc[1][f] = a;
        g_sh[1][f] = (b2[f] - m2[f]) * a + be2[f];
    } else if (L == 2 && f < FOUT) {
        g_sc[2][f] = 1.0f;
        g_sh[2][f] = b3[f];
    }
}

// ----------------------------------------------------------------------------
// SIMT GEMM: g_xw[i,f] = sum_k X[i,k] * W[f,k]
// BM=128, BK=16, TM=8, TN=BN/16, 256 threads, float4 global loads.
// ----------------------------------------------------------------------------
template <int KDIM, int BN, int TN, bool FROM_H>
__global__ void gemm_xwT(const float* __restrict__ Xext, const float* __restrict__ W) {
    constexpr int BM = 128, BK = 16, TM = 8;
    constexpr int CT = BN / TN;          // 16
    static_assert(CT == 16, "");
    const float* __restrict__ X = FROM_H ? (const float*)g_h : Xext;
    float* __restrict__ Y = g_xw;
    __shared__ float xs[BK][BM];         // stride 128 floats (aligned)
    __shared__ float ws[BK][BN + 4];
    int tid = threadIdx.x;
    int tx = tid % CT, ty = tid / CT;    // ty in 0..15
    int row0 = blockIdx.x * BM;
    float acc[TM][TN] = {};

    const float4* __restrict__ X4 = reinterpret_cast<const float4*>(X);
    const float4* __restrict__ W4 = reinterpret_cast<const float4*>(W);
    constexpr int KD4 = KDIM / 4;

    for (int k0 = 0; k0 < KDIM; k0 += BK) {
        int kb4 = k0 / 4;
        // X tile: 128 rows x 16 k = 512 float4; 2 per thread
#pragma unroll
        for (int l = 0; l < 2; ++l) {
            int idx = tid + l * 256;           // 0..511
            int m = idx >> 2;                  // 0..127
            int kv = idx & 3;                  // float4 index within BK
            int r = row0 + m;
            float4 v = make_float4(0.f, 0.f, 0.f, 0.f);
            if (r < NN) v = X4[(size_t)r * KD4 + kb4 + kv];
            xs[kv * 4 + 0][m] = v.x;
            xs[kv * 4 + 1][m] = v.y;
            xs[kv * 4 + 2][m] = v.z;
            xs[kv * 4 + 3][m] = v.w;
        }
        // W tile: BN rows x 16 k = BN*4 float4
#pragma unroll
        for (int l = 0; l < (BN * 4 + 255) / 256; ++l) {
            int idx = tid + l * 256;
            if (idx < BN * 4) {
                int f = idx >> 2;
                int kv = idx & 3;
                float4 v = W4[(size_t)f * KD4 + kb4 + kv];
                ws[kv * 4 + 0][f] = v.x;
                ws[kv * 4 + 1][f] = v.y;
                ws[kv * 4 + 2][f] = v.z;
                ws[kv * 4 + 3][f] = v.w;
            }
        }
        __syncthreads();
#pragma unroll
        for (int kk = 0; kk < BK; ++kk) {
            float a[TM], b[TN];
#pragma unroll
            for (int m = 0; m < TM; ++m) a[m] = xs[kk][ty * TM + m];
#pragma unroll
            for (int n = 0; n < TN; ++n) b[n] = ws[kk][tx * TN + n];
#pragma unroll
            for (int m = 0; m < TM; ++m)
#pragma unroll
                for (int n = 0; n < TN; ++n) acc[m][n] += a[m] * b[n];
        }
        __syncthreads();
    }
#pragma unroll
    for (int m = 0; m < TM; ++m) {
        int r = row0 + ty * TM + m;
        if (r < NN) {
#pragma unroll
            for (int n = 0; n < TN; ++n)
                Y[(size_t)r * BN + tx * TN + n] = acc[m][n];
        }
    }
}

// ----------------------------------------------------------------------------
// CSR aggregation: one warp/node, lanes 0..F/4-1 hold a float4 feature chunk.
// out[i,:] = act( (sum_e nrm_e * xw[src_e,:] + dis[i]^2 * xw[i,:]) * sc + sh )
// ----------------------------------------------------------------------------
template <int F, bool RELU, bool TO_H, int LAYER>
__global__ void aggregate(float* __restrict__ outExt) {
    constexpr int LANES = F / 4;   // 24 (F=96) or 16 (F=64)
    int warp = blockIdx.x * (blockDim.x >> 5) + (threadIdx.x >> 5);
    if (warp >= NN) return;
    int lane = threadIdx.x & 31;
    const float4* __restrict__ xw4 = reinterpret_cast<const float4*>(g_xw);
    float* __restrict__ out = TO_H ? (float*)g_h : outExt;
    bool active = lane < LANES;

    float4 acc = make_float4(0.f, 0.f, 0.f, 0.f);
    int s = g_rowptr[warp], t = g_rowptr[warp + 1];
    for (int base = s; base < t; base += 32) {
        int idx = base + lane;
        int src = 0; float nrm = 0.f;
        if (idx < t) { src = g_src[idx]; nrm = g_norm[idx]; }
        int cnt = min(32, t - base);
        for (int j = 0; j < cnt; ++j) {
            int ssrc = __shfl_sync(0xffffffffu, src, j);
            float snrm = __shfl_sync(0xffffffffu, nrm, j);
            if (active) {
                float4 v = xw4[(size_t)ssrc * (F / 4) + lane];
                acc.x += snrm * v.x;
                acc.y += snrm * v.y;
                acc.z += snrm * v.z;
                acc.w += snrm * v.w;
            }
        }
    }
    // self loop: norm = dis[i]^2 * 1.0
    float d = g_dis[warp];
    float sn = d * d;
    if (active) {
        float4 v = xw4[(size_t)warp * (F / 4) + lane];
        acc.x += sn * v.x;
        acc.y += sn * v.y;
        acc.z += sn * v.z;
        acc.w += sn * v.w;

        const float4* sc4 = reinterpret_cast<const float4*>(g_sc[LAYER]);
        const float4* sh4 = reinterpret_cast<const float4*>(g_sh[LAYER]);
        float4 sc = sc4[lane], sh = sh4[lane];
        float4 r;
        r.x = acc.x * sc.x + sh.x;
        r.y = acc.y * sc.y + sh.y;
        r.z = acc.z * sc.z + sh.z;
        r.w = acc.w * sc.w + sh.w;
        if (RELU) {
            r.x = fmaxf(r.x, 0.f); r.y = fmaxf(r.y, 0.f);
            r.z = fmaxf(r.z, 0.f); r.w = fmaxf(r.w, 0.f);
        }
        reinterpret_cast<float4*>(out)[(size_t)warp * (F / 4) + lane] = r;
    }
}

// ----------------------------------------------------------------------------
// Launch — kernel launches only (graph-capturable)
// ----------------------------------------------------------------------------
extern "C" void kernel_launch(void* const* d_in, const int* in_sizes, int n_in,
                              void* d_out, int out_size) {
    const float* x   = (const float*)d_in[0];
    const int*   ei  = (const int*)d_in[1];       // int32 (JAX x64 disabled)
    const float* ew  = (const float*)d_in[2];
    const float* W1  = (const float*)d_in[3];
    const float* b1  = (const float*)d_in[4];
    const float* W2  = (const float*)d_in[5];
    const float* b2  = (const float*)d_in[6];
    const float* W3  = (const float*)d_in[7];
    const float* b3  = (const float*)d_in[8];
    const float* g1  = (const float*)d_in[9];
    const float* be1 = (const float*)d_in[10];
    const float* m1  = (const float*)d_in[11];
    const float* v1  = (const float*)d_in[12];
    const float* g2  = (const float*)d_in[13];
    const float* be2 = (const float*)d_in[14];
    const float* m2  = (const float*)d_in[15];
    const float* v2  = (const float*)d_in[16];
    float* out = (float*)d_out;

    const int nbN    = (NN + 255) / 256;
    const int nbE    = (EE + 255) / 256;
    const int nbScan = (NN + 1023) / 1024;   // 49

    zero_init<<<nbN, 256>>>();
    deg_count<<<nbE, 256>>>(ei, ew);
    scan_block<<<nbScan, 1024>>>();          // also computes g_dis
    scan_sums<<<1, 32>>>(nbScan);
    scan_add<<<nbScan, 1024>>>();
    fill_csr<<<nbE, 256>>>(ei, ew);
    affine_all<<<3, FH>>>(g1, be1, m1, v1, b1, g2, be2, m2, v2, b2, b3);

    const int gemmBlocks = (NN + 127) / 128;   // 391
    const int aggBlocks  = (NN + 7) / 8;       // 8 warps/block

    gemm_xwT<FIN, FH, 6, false><<<gemmBlocks, 256>>>(x, W1);
    aggregate<FH, true, true, 0><<<aggBlocks, 256>>>(nullptr);

    gemm_xwT<FH, FH, 6, true><<<gemmBlocks, 256>>>(nullptr, W2);
    aggregate<FH, true, true, 1><<<aggBlocks, 256>>>(nullptr);

    gemm_xwT<FH, FOUT, 4, true><<<gemmBlocks, 256>>>(nullptr, W3);
    aggregate<FOUT, false, false, 2><<<aggBlocks, 256>>>(out);
}

// round 6
// speedup vs baseline: 1.2488x; 1.2024x over previous
#include <cuda_runtime.h>
#include <cstdint>

#define NN 50000
#define EE 800000
#define FIN 128
#define FH 96
#define FOUT 64
#define BN_EPS 1e-5f

// ----------------------------------------------------------------------------
// Device scratch (static; no cudaMalloc anywhere)
// ----------------------------------------------------------------------------
__device__ float g_deg[NN];
__device__ float g_dis[NN];
__device__ int   g_cnt[NN];
__device__ int   g_cursor[NN];
__device__ int   g_excl[NN];
__device__ int   g_bsums[64];
__device__ int   g_rowptr[NN + 1];
__device__ int   g_src[EE];
__device__ float g_norm[EE];
__device__ float g_xw[(size_t)NN * FH];
__device__ float g_h[(size_t)NN * FH];
__device__ float g_sc[3][FH];
__device__ float g_sh[3][FH];

// ----------------------------------------------------------------------------
// Graph-norm + CSR build (edge_index is int32; col = ei[EE + e])
// ----------------------------------------------------------------------------
__global__ void zero_init() {
    int i = blockIdx.x * blockDim.x + threadIdx.x;
    if (i < NN) { g_deg[i] = 0.f; g_cnt[i] = 0; g_cursor[i] = 0; }
}

__global__ void deg_count(const int* __restrict__ ei, const float* __restrict__ ew) {
    int e = blockIdx.x * blockDim.x + threadIdx.x;
    if (e >= EE) return;
    int c = ei[EE + e];
    atomicAdd(&g_deg[c], ew[e]);
    atomicAdd(&g_cnt[c], 1);
}

__global__ void scan_block() {
    __shared__ int sh[1024];
    int tid = threadIdx.x;
    int i = blockIdx.x * 1024 + tid;
    int v = (i < NN) ? g_cnt[i] : 0;
    if (i < NN) g_dis[i] = rsqrtf(g_deg[i] + 1.0f);
    sh[tid] = v;
    __syncthreads();
    for (int off = 1; off < 1024; off <<= 1) {
        int t = (tid >= off) ? sh[tid - off] : 0;
        __syncthreads();
        sh[tid] += t;
        __syncthreads();
    }
    if (i < NN) g_excl[i] = sh[tid] - v;
    if (tid == 1023) g_bsums[blockIdx.x] = sh[1023];
}

__global__ void scan_sums(int nb) {
    if (threadIdx.x == 0) {
        int acc = 0;
        for (int b = 0; b < nb; ++b) { int t = g_bsums[b]; g_bsums[b] = acc; acc += t; }
    }
}

__global__ void scan_add() {
    int i = blockIdx.x * 1024 + threadIdx.x;
    if (i < NN) g_rowptr[i] = g_excl[i] + g_bsums[blockIdx.x];
    if (blockIdx.x == 0 && threadIdx.x == 0) g_rowptr[NN] = EE;
}

__global__ void fill_csr(const int* __restrict__ ei, const float* __restrict__ ew) {
    int e = blockIdx.x * blockDim.x + threadIdx.x;
    if (e >= EE) return;
    int r = ei[e];
    int c = ei[EE + e];
    float nrm = g_dis[r] * ew[e] * g_dis[c];
    int pos = g_rowptr[c] + atomicAdd(&g_cursor[c], 1);
    g_src[pos] = r;
    g_norm[pos] = nrm;
}

// ----------------------------------------------------------------------------
// Folded affine for all 3 layers in one launch. blockIdx.x = layer.
// ----------------------------------------------------------------------------
__global__ void affine_all(const float* g1, const float* be1, const float* m1, const float* v1, const float* b1,
                           const float* g2, const float* be2, const float* m2, const float* v2, const float* b2,
                           const float* b3) {
    int f = threadIdx.x;
    int L = blockIdx.x;
    if (L == 0 && f < FH) {
        float a = g1[f] * rsqrtf(v1[f] + BN_EPS);
        g_sc[0][f] = a;
        g_sh[0][f] = (b1[f] - m1[f]) * a + be1[f];
    } else if (L == 1 && f < FH) {
        float a = g2[f] * rsqrtf(v2[f] + BN_EPS);
        g_sc[1][f] = a;
        g_sh[1][f] = (b2[f] - m2[f]) * a + be2[f];
    } else if (L == 2 && f < FOUT) {
        g_sc[2][f] = 1.0f;
        g_sh[2][f] = b3[f];
    }
}

// ----------------------------------------------------------------------------
// tf32 tensor-core GEMM: g_xw[i,f] = sum_k X[i,k] * W[f,k]
// mma.sync m16n8k8 tf32. 256 threads = 8 warps (4 along M x 2 along N).
// BM=128 rows, BN = full output width (96 or 64), BK=32.
// ----------------------------------------------------------------------------
__device__ __forceinline__ float f2tf32(float x) {
    uint32_t r;
    asm("cvt.rna.tf32.f32 %0, %1;" : "=r"(r) : "f"(x));
    float out;
    asm("mov.b32 %0, %1;" : "=f"(out) : "r"(r));
    return out;
}

template <int KDIM, int BN, bool FROM_H>
__global__ void __launch_bounds__(256, 1) gemm_tc(const float* __restrict__ Xext,
                                                  const float* __restrict__ W) {
    constexpr int BM = 128, BK = 32;
    constexpr int WN = BN / 2;          // per-warp N tile (48 or 32)
    constexpr int NF = WN / 8;          // n-frags per warp (6 or 4)
    constexpr int ASTR = BM + 8;        // 136: bank=(8k+m)%32 distinct per lane
    constexpr int BSTR = BN + 8;        // 104 / 72: same property

    const float* __restrict__ X = FROM_H ? (const float*)g_h : Xext;
    float* __restrict__ Y = g_xw;

    __shared__ float As[BK][ASTR];      // [k][m], tf32-rounded
    __shared__ float Bs[BK][BSTR];      // [k][n], tf32-rounded

    int tid = threadIdx.x;
    int wid = tid >> 5, lane = tid & 31;
    int wm = wid & 3, wn = wid >> 2;    // warp grid 4 x 2
    int g = lane >> 2, tig = lane & 3;  // groupID, threadID-in-group
    int row0 = blockIdx.x * BM;
    int m0 = wm * 32;                   // warp m base within block
    int n0 = wn * WN;                   // warp n base within block

    float acc[2][NF][4];
#pragma unroll
    for (int mi = 0; mi < 2; ++mi)
#pragma unroll
        for (int ni = 0; ni < NF; ++ni)
#pragma unroll
            for (int c = 0; c < 4; ++c) acc[mi][ni][c] = 0.f;

    const float4* __restrict__ X4 = reinterpret_cast<const float4*>(X);
    const float4* __restrict__ W4 = reinterpret_cast<const float4*>(W);
    constexpr int KD4 = KDIM / 4;

    for (int k0 = 0; k0 < KDIM; k0 += BK) {
        int kb4 = k0 >> 2;
        // Fill A: 128 rows x 32 k = 1024 float4, 4 per thread
#pragma unroll
        for (int t = 0; t < 4; ++t) {
            int idx = tid + t * 256;           // 0..1023
            int m = idx >> 3;                  // 0..127
            int kq = idx & 7;                  // float4 within BK
            int r = row0 + m;
            float4 v = make_float4(0.f, 0.f, 0.f, 0.f);
            if (r < NN) v = X4[(size_t)r * KD4 + kb4 + kq];
            As[kq * 4 + 0][m] = f2tf32(v.x);
            As[kq * 4 + 1][m] = f2tf32(v.y);
            As[kq * 4 + 2][m] = f2tf32(v.z);
            As[kq * 4 + 3][m] = f2tf32(v.w);
        }
        // Fill B: BN rows x 32 k = BN*8 float4
#pragma unroll
        for (int t = 0; t < (BN * 8 + 255) / 256; ++t) {
            int idx = tid + t * 256;
            if (idx < BN * 8) {
                int f = idx >> 3;
                int kq = idx & 7;
                float4 v = W4[(size_t)f * KD4 + kb4 + kq];
                Bs[kq * 4 + 0][f] = f2tf32(v.x);
                Bs[kq * 4 + 1][f] = f2tf32(v.y);
                Bs[kq * 4 + 2][f] = f2tf32(v.z);
                Bs[kq * 4 + 3][f] = f2tf32(v.w);
            }
        }
        __syncthreads();
#pragma unroll
        for (int kf = 0; kf < BK / 8; ++kf) {
            int kb = kf * 8;
            uint32_t a[2][4];
#pragma unroll
            for (int mi = 0; mi < 2; ++mi) {
                int mb = m0 + mi * 16;
                a[mi][0] = __float_as_uint(As[kb + tig][mb + g]);
                a[mi][1] = __float_as_uint(As[kb + tig][mb + g + 8]);
                a[mi][2] = __float_as_uint(As[kb + tig + 4][mb + g]);
                a[mi][3] = __float_as_uint(As[kb + tig + 4][mb + g + 8]);
            }
            uint32_t b[NF][2];
#pragma unroll
            for (int ni = 0; ni < NF; ++ni) {
                int nb = n0 + ni * 8;
                b[ni][0] = __float_as_uint(Bs[kb + tig][nb + g]);
                b[ni][1] = __float_as_uint(Bs[kb + tig + 4][nb + g]);
            }
#pragma unroll
            for (int mi = 0; mi < 2; ++mi)
#pragma unroll
                for (int ni = 0; ni < NF; ++ni) {
                    asm volatile(
                        "mma.sync.aligned.m16n8k8.row.col.f32.tf32.tf32.f32 "
                        "{%0,%1,%2,%3},{%4,%5,%6,%7},{%8,%9},{%0,%1,%2,%3};"
                        : "+f"(acc[mi][ni][0]), "+f"(acc[mi][ni][1]),
                          "+f"(acc[mi][ni][2]), "+f"(acc[mi][ni][3])
                        : "r"(a[mi][0]), "r"(a[mi][1]), "r"(a[mi][2]), "r"(a[mi][3]),
                          "r"(b[ni][0]), "r"(b[ni][1]));
                }
        }
        __syncthreads();
    }

    // Epilogue: c0:(g, 2*tig) c1:(g, 2*tig+1) c2:(g+8, 2*tig) c3:(g+8, 2*tig+1)
#pragma unroll
    for (int mi = 0; mi < 2; ++mi) {
        int r0 = row0 + m0 + mi * 16 + g;
        int r1 = r0 + 8;
#pragma unroll
        for (int ni = 0; ni < NF; ++ni) {
            int c = n0 + ni * 8 + tig * 2;
            if (r0 < NN) {
                float2 v = make_float2(acc[mi][ni][0], acc[mi][ni][1]);
                *reinterpret_cast<float2*>(&Y[(size_t)r0 * BN + c]) = v;
            }
            if (r1 < NN) {
                float2 v = make_float2(acc[mi][ni][2], acc[mi][ni][3]);
                *reinterpret_cast<float2*>(&Y[(size_t)r1 * BN + c]) = v;
            }
        }
    }
}

// ----------------------------------------------------------------------------
// CSR aggregation: one warp/node, lanes 0..F/4-1 hold a float4 feature chunk.
// ----------------------------------------------------------------------------
template <int F, bool RELU, bool TO_H, int LAYER>
__global__ void aggregate(float* __restrict__ outExt) {
    constexpr int LANES = F / 4;
    int warp = blockIdx.x * (blockDim.x >> 5) + (threadIdx.x >> 5);
    if (warp >= NN) return;
    int lane = threadIdx.x & 31;
    const float4* __restrict__ xw4 = reinterpret_cast<const float4*>(g_xw);
    float* __restrict__ out = TO_H ? (float*)g_h : outExt;
    bool active = lane < LANES;

    float4 acc = make_float4(0.f, 0.f, 0.f, 0.f);
    int s = g_rowptr[warp], t = g_rowptr[warp + 1];
    for (int base = s; base < t; base += 32) {
        int idx = base + lane;
        int src = 0; float nrm = 0.f;
        if (idx < t) { src = g_src[idx]; nrm = g_norm[idx]; }
        int cnt = min(32, t - base);
        for (int j = 0; j < cnt; ++j) {
            int ssrc = __shfl_sync(0xffffffffu, src, j);
            float snrm = __shfl_sync(0xffffffffu, nrm, j);
            if (active) {
                float4 v = xw4[(size_t)ssrc * (F / 4) + lane];
                acc.x += snrm * v.x;
                acc.y += snrm * v.y;
                acc.z += snrm * v.z;
                acc.w += snrm * v.w;
            }
        }
    }
    float d = g_dis[warp];
    float sn = d * d;
    if (active) {
        float4 v = xw4[(size_t)warp * (F / 4) + lane];
        acc.x += sn * v.x;
        acc.y += sn * v.y;
        acc.z += sn * v.z;
        acc.w += sn * v.w;

        const float4* sc4 = reinterpret_cast<const float4*>(g_sc[LAYER]);
        const float4* sh4 = reinterpret_cast<const float4*>(g_sh[LAYER]);
        float4 sc = sc4[lane], sh = sh4[lane];
        float4 r;
        r.x = acc.x * sc.x + sh.x;
        r.y = acc.y * sc.y + sh.y;
        r.z = acc.z * sc.z + sh.z;
        r.w = acc.w * sc.w + sh.w;
        if (RELU) {
            r.x = fmaxf(r.x, 0.f); r.y = fmaxf(r.y, 0.f);
            r.z = fmaxf(r.z, 0.f); r.w = fmaxf(r.w, 0.f);
        }
        reinterpret_cast<float4*>(out)[(size_t)warp * (F / 4) + lane] = r;
    }
}

// ----------------------------------------------------------------------------
// Launch — kernel launches only (graph-capturable)
// ----------------------------------------------------------------------------
extern "C" void kernel_launch(void* const* d_in, const int* in_sizes, int n_in,
                              void* d_out, int out_size) {
    const float* x   = (const float*)d_in[0];
    const int*   ei  = (const int*)d_in[1];       // int32 (JAX x64 disabled)
    const float* ew  = (const float*)d_in[2];
    const float* W1  = (const float*)d_in[3];
    const float* b1  = (const float*)d_in[4];
    const float* W2  = (const float*)d_in[5];
    const float* b2  = (const float*)d_in[6];
    const float* W3  = (const float*)d_in[7];
    const float* b3  = (const float*)d_in[8];
    const float* g1  = (const float*)d_in[9];
    const float* be1 = (const float*)d_in[10];
    const float* m1  = (const float*)d_in[11];
    const float* v1  = (const float*)d_in[12];
    const float* g2  = (const float*)d_in[13];
    const float* be2 = (const float*)d_in[14];
    const float* m2  = (const float*)d_in[15];
    const float* v2  = (const float*)d_in[16];
    float* out = (float*)d_out;

    const int nbN    = (NN + 255) / 256;
    const int nbE    = (EE + 255) / 256;
    const int nbScan = (NN + 1023) / 1024;

    zero_init<<<nbN, 256>>>();
    deg_count<<<nbE, 256>>>(ei, ew);
    scan_block<<<nbScan, 1024>>>();
    scan_sums<<<1, 32>>>(nbScan);
    scan_add<<<nbScan, 1024>>>();
    fill_csr<<<nbE, 256>>>(ei, ew);
    affine_all<<<3, FH>>>(g1, be1, m1, v1, b1, g2, be2, m2, v2, b2, b3);

    const int gemmBlocks = (NN + 127) / 128;   // 391
    const int aggBlocks  = (NN + 7) / 8;

    gemm_tc<FIN, FH, false><<<gemmBlocks, 256>>>(x, W1);
    aggregate<FH, true, true, 0><<<aggBlocks, 256>>>(nullptr);

    gemm_tc<FH, FH, true><<<gemmBlocks, 256>>>(nullptr, W2);
    aggregate<FH, true, true, 1><<<aggBlocks, 256>>>(nullptr);

    gemm_tc<FH, FOUT, true><<<gemmBlocks, 256>>>(nullptr, W3);
    aggregate<FOUT, false, false, 2><<<aggBlocks, 256>>>(out);
}

// round 7
// speedup vs baseline: 1.3041x; 1.0443x over previous
#include <cuda_runtime.h>
#include <cstdint>

#define NN 50000
#define EE 800000
#define FIN 128
#define FH 96
#define FOUT 64
#define BN_EPS 1e-5f
#define SCAN_NB 49            // ceil(50000/1024)

// ----------------------------------------------------------------------------
// Device scratch (static; no cudaMalloc anywhere).
// Zero-state invariant: every call leaves g_deg/g_cnt/g_cursor/g_scanstate
// ready (zeroed) for the next call; first call sees load-time zeros.
// ----------------------------------------------------------------------------
__device__ float g_deg[NN];
__device__ float g_dis[NN];
__device__ int   g_cnt[NN];
__device__ int   g_cursor[NN];
__device__ unsigned long long g_scanstate[SCAN_NB];
__device__ int   g_rowptr[NN + 1];
__device__ int   g_src[EE];
__device__ float g_norm[EE];
__device__ float g_xw[(size_t)NN * FH];
__device__ float g_h[(size_t)NN * FH];
__device__ float g_sc[3][FH];
__device__ float g_sh[3][FH];

// ----------------------------------------------------------------------------
// 1) deg_count: edge-parallel degree accumulation. Block 0 also zeroes the
//    lookback scan state for the NEXT kernel (stream-ordered).
// ----------------------------------------------------------------------------
__global__ void deg_count(const int* __restrict__ ei, const float* __restrict__ ew) {
    int e = blockIdx.x * blockDim.x + threadIdx.x;
    if (blockIdx.x == 0 && threadIdx.x < SCAN_NB) g_scanstate[threadIdx.x] = 0ULL;
    if (e >= EE) return;
    int c = ei[EE + e];
    atomicAdd(&g_deg[c], ew[e]);
    atomicAdd(&g_cnt[c], 1);
}

// ----------------------------------------------------------------------------
// 2) Single-kernel exclusive scan of g_cnt -> g_rowptr (decoupled lookback).
//    Also computes g_dis and self-restores g_deg/g_cnt/g_cursor to zero.
//    49 blocks x 1024 threads: all resident in one wave (148 SMs) -> no
//    deadlock from spinning.
// ----------------------------------------------------------------------------
#define FLAG_AGG (1ULL << 62)
#define FLAG_INC (2ULL << 62)
#define VAL_MASK 0xffffffffULL

__global__ void scan_lookback() {
    __shared__ int sh[1024];
    __shared__ int s_prefix;
    int tid = threadIdx.x;
    int bid = blockIdx.x;
    int i = bid * 1024 + tid;
    int v = (i < NN) ? g_cnt[i] : 0;
    sh[tid] = v;
    __syncthreads();
#pragma unroll
    for (int off = 1; off < 1024; off <<= 1) {
        int t = (tid >= off) ? sh[tid - off] : 0;
        __syncthreads();
        sh[tid] += t;
        __syncthreads();
    }
    int total = sh[1023];

    if (tid == 0) {
        if (bid == 0) {
            s_prefix = 0;
            atomicExch(&g_scanstate[0], FLAG_INC | (unsigned long long)total);
            g_rowptr[NN] = EE;
        } else {
            atomicExch(&g_scanstate[bid], FLAG_AGG | (unsigned long long)total);
            int p = bid - 1;
            long long prefix = 0;
            while (true) {
                unsigned long long s = *(volatile unsigned long long*)&g_scanstate[p];
                unsigned long long flag = s & (3ULL << 62);
                if (flag == FLAG_INC) { prefix += (long long)(s & VAL_MASK); break; }
                if (flag == FLAG_AGG) { prefix += (long long)(s & VAL_MASK); --p; }
                else __nanosleep(32);
            }
            atomicExch(&g_scanstate[bid], FLAG_INC | (unsigned long long)(prefix + total));
            s_prefix = (int)prefix;
        }
    }
    __syncthreads();
    if (i < NN) {
        g_rowptr[i] = s_prefix + sh[tid] - v;   // exclusive prefix
        g_dis[i] = rsqrtf(g_deg[i] + 1.0f);     // self-loop weight 1 => deg>0
        g_deg[i] = 0.f;                         // restore zero-state
        g_cnt[i] = 0;
        g_cursor[i] = 0;
    }
}

// ----------------------------------------------------------------------------
// 3) fill_csr + folded BN/bias affine (extra blocks past the edge range).
// ----------------------------------------------------------------------------
__global__ void fill_csr_affine(const int* __restrict__ ei, const float* __restrict__ ew,
                                int nbE,
                                const float* g1, const float* be1, const float* m1, const float* v1, const float* b1,
                                const float* g2, const float* be2, const float* m2, const float* v2, const float* b2,
                                const float* b3) {
    if (blockIdx.x >= (unsigned)nbE) {
        int L = blockIdx.x - nbE;
        int f = threadIdx.x;
        if (L == 0 && f < FH) {
            float a = g1[f] * rsqrtf(v1[f] + BN_EPS);
            g_sc[0][f] = a;
            g_sh[0][f] = (b1[f] - m1[f]) * a + be1[f];
        } else if (L == 1 && f < FH) {
            float a = g2[f] * rsqrtf(v2[f] + BN_EPS);
            g_sc[1][f] = a;
            g_sh[1][f] = (b2[f] - m2[f]) * a + be2[f];
        } else if (L == 2 && f < FOUT) {
            g_sc[2][f] = 1.0f;
            g_sh[2][f] = b3[f];
        }
        return;
    }
    int e = blockIdx.x * blockDim.x + threadIdx.x;
    if (e >= EE) return;
    int r = ei[e];
    int c = ei[EE + e];
    float nrm = g_dis[r] * ew[e] * g_dis[c];
    int pos = g_rowptr[c] + atomicAdd(&g_cursor[c], 1);
    g_src[pos] = r;
    g_norm[pos] = nrm;
}

// ----------------------------------------------------------------------------
// tf32 tensor-core GEMM: g_xw[i,f] = sum_k X[i,k] * W[f,k]
// mma.sync m16n8k8 tf32. 256 threads = 8 warps (4 M x 2 N). BM=128, BK=32.
// ----------------------------------------------------------------------------
__device__ __forceinline__ float f2tf32(float x) {
    uint32_t r;
    asm("cvt.rna.tf32.f32 %0, %1;" : "=r"(r) : "f"(x));
    float out;
    asm("mov.b32 %0, %1;" : "=f"(out) : "r"(r));
    return out;
}

template <int KDIM, int BN, bool FROM_H>
__global__ void __launch_bounds__(256, 1) gemm_tc(const float* __restrict__ Xext,
                                                  const float* __restrict__ W) {
    constexpr int BM = 128, BK = 32;
    constexpr int WN = BN / 2;
    constexpr int NF = WN / 8;
    constexpr int ASTR = BM + 8;
    constexpr int BSTR = BN + 8;

    const float* __restrict__ X = FROM_H ? (const float*)g_h : Xext;
    float* __restrict__ Y = g_xw;

    __shared__ float As[BK][ASTR];
    __shared__ float Bs[BK][BSTR];

    int tid = threadIdx.x;
    int wid = tid >> 5, lane = tid & 31;
    int wm = wid & 3, wn = wid >> 2;
    int g = lane >> 2, tig = lane & 3;
    int row0 = blockIdx.x * BM;
    int m0 = wm * 32;
    int n0 = wn * WN;

    float acc[2][NF][4];
#pragma unroll
    for (int mi = 0; mi < 2; ++mi)
#pragma unroll
        for (int ni = 0; ni < NF; ++ni)
#pragma unroll
            for (int c = 0; c < 4; ++c) acc[mi][ni][c] = 0.f;

    const float4* __restrict__ X4 = reinterpret_cast<const float4*>(X);
    const float4* __restrict__ W4 = reinterpret_cast<const float4*>(W);
    constexpr int KD4 = KDIM / 4;

    for (int k0 = 0; k0 < KDIM; k0 += BK) {
        int kb4 = k0 >> 2;
#pragma unroll
        for (int t = 0; t < 4; ++t) {
            int idx = tid + t * 256;
            int m = idx >> 3;
            int kq = idx & 7;
            int r = row0 + m;
            float4 v = make_float4(0.f, 0.f, 0.f, 0.f);
            if (r < NN) v = X4[(size_t)r * KD4 + kb4 + kq];
            As[kq * 4 + 0][m] = f2tf32(v.x);
            As[kq * 4 + 1][m] = f2tf32(v.y);
            As[kq * 4 + 2][m] = f2tf32(v.z);
            As[kq * 4 + 3][m] = f2tf32(v.w);
        }
#pragma unroll
        for (int t = 0; t < (BN * 8 + 255) / 256; ++t) {
            int idx = tid + t * 256;
            if (idx < BN * 8) {
                int f = idx >> 3;
                int kq = idx & 7;
                float4 v = W4[(size_t)f * KD4 + kb4 + kq];
                Bs[kq * 4 + 0][f] = f2tf32(v.x);
                Bs[kq * 4 + 1][f] = f2tf32(v.y);
                Bs[kq * 4 + 2][f] = f2tf32(v.z);
                Bs[kq * 4 + 3][f] = f2tf32(v.w);
            }
        }
        __syncthreads();
#pragma unroll
        for (int kf = 0; kf < BK / 8; ++kf) {
            int kb = kf * 8;
            uint32_t a[2][4];
#pragma unroll
            for (int mi = 0; mi < 2; ++mi) {
                int mb = m0 + mi * 16;
                a[mi][0] = __float_as_uint(As[kb + tig][mb + g]);
                a[mi][1] = __float_as_uint(As[kb + tig][mb + g + 8]);
                a[mi][2] = __float_as_uint(As[kb + tig + 4][mb + g]);
                a[mi][3] = __float_as_uint(As[kb + tig + 4][mb + g + 8]);
            }
            uint32_t b[NF][2];
#pragma unroll
            for (int ni = 0; ni < NF; ++ni) {
                int nb = n0 + ni * 8;
                b[ni][0] = __float_as_uint(Bs[kb + tig][nb + g]);
                b[ni][1] = __float_as_uint(Bs[kb + tig + 4][nb + g]);
            }
#pragma unroll
            for (int mi = 0; mi < 2; ++mi)
#pragma unroll
                for (int ni = 0; ni < NF; ++ni) {
                    asm volatile(
                        "mma.sync.aligned.m16n8k8.row.col.f32.tf32.tf32.f32 "
                        "{%0,%1,%2,%3},{%4,%5,%6,%7},{%8,%9},{%0,%1,%2,%3};"
                        : "+f"(acc[mi][ni][0]), "+f"(acc[mi][ni][1]),
                          "+f"(acc[mi][ni][2]), "+f"(acc[mi][ni][3])
                        : "r"(a[mi][0]), "r"(a[mi][1]), "r"(a[mi][2]), "r"(a[mi][3]),
                          "r"(b[ni][0]), "r"(b[ni][1]));
                }
        }
        __syncthreads();
    }

#pragma unroll
    for (int mi = 0; mi < 2; ++mi) {
        int r0 = row0 + m0 + mi * 16 + g;
        int r1 = r0 + 8;
#pragma unroll
        for (int ni = 0; ni < NF; ++ni) {
            int c = n0 + ni * 8 + tig * 2;
            if (r0 < NN) {
                float2 v = make_float2(acc[mi][ni][0], acc[mi][ni][1]);
                *reinterpret_cast<float2*>(&Y[(size_t)r0 * BN + c]) = v;
            }
            if (r1 < NN) {
                float2 v = make_float2(acc[mi][ni][2], acc[mi][ni][3]);
                *reinterpret_cast<float2*>(&Y[(size_t)r1 * BN + c]) = v;
            }
        }
    }
}

// ----------------------------------------------------------------------------
// CSR aggregation: one warp/node, lanes 0..F/4-1 hold a float4 feature chunk.
// Dual accumulators (unroll-by-2 over edges) to double ILP.
// ----------------------------------------------------------------------------
template <int F, bool RELU, bool TO_H, int LAYER>
__global__ void aggregate(float* __restrict__ outExt) {
    constexpr int LANES = F / 4;
    int warp = blockIdx.x * (blockDim.x >> 5) + (threadIdx.x >> 5);
    if (warp >= NN) return;
    int lane = threadIdx.x & 31;
    const float4* __restrict__ xw4 = reinterpret_cast<const float4*>(g_xw);
    float* __restrict__ out = TO_H ? (float*)g_h : outExt;
    bool active = lane < LANES;

    float4 acc0 = make_float4(0.f, 0.f, 0.f, 0.f);
    float4 acc1 = make_float4(0.f, 0.f, 0.f, 0.f);
    int s = g_rowptr[warp], t = g_rowptr[warp + 1];
    for (int base = s; base < t; base += 32) {
        int idx = base + lane;
        int src = 0; float nrm = 0.f;
        if (idx < t) { src = g_src[idx]; nrm = g_norm[idx]; }
        int cnt = min(32, t - base);
        int j = 0;
        for (; j + 1 < cnt; j += 2) {
            int s0 = __shfl_sync(0xffffffffu, src, j);
            float n0 = __shfl_sync(0xffffffffu, nrm, j);
            int s1 = __shfl_sync(0xffffffffu, src, j + 1);
            float n1 = __shfl_sync(0xffffffffu, nrm, j + 1);
            if (active) {
                float4 v0 = xw4[(size_t)s0 * (F / 4) + lane];
                float4 v1 = xw4[(size_t)s1 * (F / 4) + lane];
                acc0.x += n0 * v0.x; acc0.y += n0 * v0.y;
                acc0.z += n0 * v0.z; acc0.w += n0 * v0.w;
                acc1.x += n1 * v1.x; acc1.y += n1 * v1.y;
                acc1.z += n1 * v1.z; acc1.w += n1 * v1.w;
            }
        }
        if (j < cnt) {
            int s0 = __shfl_sync(0xffffffffu, src, j);
            float n0 = __shfl_sync(0xffffffffu, nrm, j);
            if (active) {
                float4 v0 = xw4[(size_t)s0 * (F / 4) + lane];
                acc0.x += n0 * v0.x; acc0.y += n0 * v0.y;
                acc0.z += n0 * v0.z; acc0.w += n0 * v0.w;
            }
        }
    }
    float d = g_dis[warp];
    float sn = d * d;
    if (active) {
        float4 v = xw4[(size_t)warp * (F / 4) + lane];
        acc0.x += sn * v.x + acc1.x;
        acc0.y += sn * v.y + acc1.y;
        acc0.z += sn * v.z + acc1.z;
        acc0.w += sn * v.w + acc1.w;

        const float4* sc4 = reinterpret_cast<const float4*>(g_sc[LAYER]);
        const float4* sh4 = reinterpret_cast<const float4*>(g_sh[LAYER]);
        float4 sc = sc4[lane], sh = sh4[lane];
        float4 r;
        r.x = acc0.x * sc.x + sh.x;
        r.y = acc0.y * sc.y + sh.y;
        r.z = acc0.z * sc.z + sh.z;
        r.w = acc0.w * sc.w + sh.w;
        if (RELU) {
            r.x = fmaxf(r.x, 0.f); r.y = fmaxf(r.y, 0.f);
            r.z = fmaxf(r.z, 0.f); r.w = fmaxf(r.w, 0.f);
        }
        reinterpret_cast<float4*>(out)[(size_t)warp * (F / 4) + lane] = r;
    }
}

// ----------------------------------------------------------------------------
// Launch — 9 kernel launches, graph-capturable.
// ----------------------------------------------------------------------------
extern "C" void kernel_launch(void* const* d_in, const int* in_sizes, int n_in,
                              void* d_out, int out_size) {
    const float* x   = (const float*)d_in[0];
    const int*   ei  = (const int*)d_in[1];       // int32 (JAX x64 disabled)
    const float* ew  = (const float*)d_in[2];
    const float* W1  = (const float*)d_in[3];
    const float* b1  = (const float*)d_in[4];
    const float* W2  = (const float*)d_in[5];
    const float* b2  = (const float*)d_in[6];
    const float* W3  = (const float*)d_in[7];
    const float* b3  = (const float*)d_in[8];
    const float* g1  = (const float*)d_in[9];
    const float* be1 = (const float*)d_in[10];
    const float* m1  = (const float*)d_in[11];
    const float* v1  = (const float*)d_in[12];
    const float* g2  = (const float*)d_in[13];
    const float* be2 = (const float*)d_in[14];
    const float* m2  = (const float*)d_in[15];
    const float* v2  = (const float*)d_in[16];
    float* out = (float*)d_out;

    const int nbE = (EE + 255) / 256;   // 3125

    deg_count<<<nbE, 256>>>(ei, ew);
    scan_lookback<<<SCAN_NB, 1024>>>();
    fill_csr_affine<<<nbE + 3, 256>>>(ei, ew, nbE,
                                      g1, be1, m1, v1, b1,
                                      g2, be2, m2, v2, b2, b3);

    const int gemmBlocks = (NN + 127) / 128;   // 391
    const int aggBlocks  = (NN + 7) / 8;

    gemm_tc<FIN, FH, false><<<gemmBlocks, 256>>>(x, W1);
    aggregate<FH, true, true, 0><<<aggBlocks, 256>>>(nullptr);

    gemm_tc<FH, FH, true><<<gemmBlocks, 256>>>(nullptr, W2);
    aggregate<FH, true, true, 1><<<aggBlocks, 256>>>(nullptr);

    gemm_tc<FH, FOUT, true><<<gemmBlocks, 256>>>(nullptr, W3);
    aggregate<FOUT, false, false, 2><<<aggBlocks, 256>>>(out);
}

// round 8
// speedup vs baseline: 1.3220x; 1.0137x over previous
#include <cuda_runtime.h>
#include <cstdint>

#define NN 50000
#define EE 800000
#define FIN 128
#define FH 96
#define FOUT 64
#define BN_EPS 1e-5f
#define SCAN_NB 49            // ceil(50000/1024)

// ----------------------------------------------------------------------------
// Device scratch (static; no cudaMalloc anywhere).
// Zero-state invariant: every call leaves g_deg/g_cnt/g_cursor/g_scanstate
// zeroed for the next call; first call sees load-time zeros.
// ----------------------------------------------------------------------------
__device__ float g_deg[NN];
__device__ float g_dis[NN];
__device__ int   g_cnt[NN];
__device__ int   g_cursor[NN];
__device__ unsigned long long g_scanstate[SCAN_NB];
__device__ int   g_rowptr[NN + 1];
__device__ int   g_src[EE];
__device__ float g_norm[EE];
__device__ float g_xw[(size_t)NN * FH];
__device__ float g_h[(size_t)NN * FH];
__device__ float g_sc[3][FH];
__device__ float g_sh[3][FH];

// ----------------------------------------------------------------------------
// 1) deg_count (+ zero scan state for next kernel)
// ----------------------------------------------------------------------------
__global__ void deg_count(const int* __restrict__ ei, const float* __restrict__ ew) {
    int e = blockIdx.x * blockDim.x + threadIdx.x;
    if (blockIdx.x == 0 && threadIdx.x < SCAN_NB) g_scanstate[threadIdx.x] = 0ULL;
    if (e >= EE) return;
    int c = ei[EE + e];
    atomicAdd(&g_deg[c], ew[e]);
    atomicAdd(&g_cnt[c], 1);
}

// ----------------------------------------------------------------------------
// 2) Decoupled-lookback exclusive scan; also g_dis + zero-state restore.
//    49 blocks -> all resident in wave 1 -> spin is deadlock-free.
// ----------------------------------------------------------------------------
#define FLAG_AGG (1ULL << 62)
#define FLAG_INC (2ULL << 62)
#define VAL_MASK 0xffffffffULL

__global__ void scan_lookback() {
    __shared__ int sh[1024];
    __shared__ int s_prefix;
    int tid = threadIdx.x;
    int bid = blockIdx.x;
    int i = bid * 1024 + tid;
    int v = (i < NN) ? g_cnt[i] : 0;
    sh[tid] = v;
    __syncthreads();
#pragma unroll
    for (int off = 1; off < 1024; off <<= 1) {
        int t = (tid >= off) ? sh[tid - off] : 0;
        __syncthreads();
        sh[tid] += t;
        __syncthreads();
    }
    int total = sh[1023];

    if (tid == 0) {
        if (bid == 0) {
            s_prefix = 0;
            atomicExch(&g_scanstate[0], FLAG_INC | (unsigned long long)total);
            g_rowptr[NN] = EE;
        } else {
            atomicExch(&g_scanstate[bid], FLAG_AGG | (unsigned long long)total);
            int p = bid - 1;
            long long prefix = 0;
            while (true) {
                unsigned long long s = *(volatile unsigned long long*)&g_scanstate[p];
                unsigned long long flag = s & (3ULL << 62);
                if (flag == FLAG_INC) { prefix += (long long)(s & VAL_MASK); break; }
                if (flag == FLAG_AGG) { prefix += (long long)(s & VAL_MASK); --p; }
                else __nanosleep(32);
            }
            atomicExch(&g_scanstate[bid], FLAG_INC | (unsigned long long)(prefix + total));
            s_prefix = (int)prefix;
        }
    }
    __syncthreads();
    if (i < NN) {
        g_rowptr[i] = s_prefix + sh[tid] - v;
        g_dis[i] = rsqrtf(g_deg[i] + 1.0f);
        g_deg[i] = 0.f;
        g_cnt[i] = 0;
        g_cursor[i] = 0;
    }
}

// ----------------------------------------------------------------------------
// 3) fill_csr + folded BN/bias affine (3 extra blocks)
// ----------------------------------------------------------------------------
__global__ void fill_csr_affine(const int* __restrict__ ei, const float* __restrict__ ew,
                                int nbE,
                                const float* g1, const float* be1, const float* m1, const float* v1, const float* b1,
                                const float* g2, const float* be2, const float* m2, const float* v2, const float* b2,
                                const float* b3) {
    if (blockIdx.x >= (unsigned)nbE) {
        int L = blockIdx.x - nbE;
        int f = threadIdx.x;
        if (L == 0 && f < FH) {
            float a = g1[f] * rsqrtf(v1[f] + BN_EPS);
            g_sc[0][f] = a;
            g_sh[0][f] = (b1[f] - m1[f]) * a + be1[f];
        } else if (L == 1 && f < FH) {
            float a = g2[f] * rsqrtf(v2[f] + BN_EPS);
            g_sc[1][f] = a;
            g_sh[1][f] = (b2[f] - m2[f]) * a + be2[f];
        } else if (L == 2 && f < FOUT) {
            g_sc[2][f] = 1.0f;
            g_sh[2][f] = b3[f];
        }
        return;
    }
    int e = blockIdx.x * blockDim.x + threadIdx.x;
    if (e >= EE) return;
    int r = ei[e];
    int c = ei[EE + e];
    float nrm = g_dis[r] * ew[e] * g_dis[c];
    int pos = g_rowptr[c] + atomicAdd(&g_cursor[c], 1);
    g_src[pos] = r;
    g_norm[pos] = nrm;
}

// ----------------------------------------------------------------------------
// tf32 tensor-core GEMM, mma.sync m16n8k8. 256 threads (4x2 warps),
// BM=128, BK=32, 2 blocks/SM, register-staged global loads.
// ----------------------------------------------------------------------------
__device__ __forceinline__ float f2tf32(float x) {
    uint32_t r;
    asm("cvt.rna.tf32.f32 %0, %1;" : "=r"(r) : "f"(x));
    float out;
    asm("mov.b32 %0, %1;" : "=f"(out) : "r"(r));
    return out;
}

template <int KDIM, int BN, bool FROM_H>
__global__ void __launch_bounds__(256, 2) gemm_tc(const float* __restrict__ Xext,
                                                  const float* __restrict__ W) {
    constexpr int BM = 128, BK = 32;
    constexpr int WN = BN / 2;
    constexpr int NF = WN / 8;
    constexpr int ASTR = BM + 8;
    constexpr int BSTR = BN + 8;
    constexpr int NBT = (BN * 8 + 255) / 256;   // B-tile float4 loads / thread

    const float* __restrict__ X = FROM_H ? (const float*)g_h : Xext;
    float* __restrict__ Y = g_xw;

    __shared__ float As[BK][ASTR];
    __shared__ float Bs[BK][BSTR];

    int tid = threadIdx.x;
    int wid = tid >> 5, lane = tid & 31;
    int wm = wid & 3, wn = wid >> 2;
    int g = lane >> 2, tig = lane & 3;
    int row0 = blockIdx.x * BM;
    int m0 = wm * 32;
    int n0 = wn * WN;

    float acc[2][NF][4];
#pragma unroll
    for (int mi = 0; mi < 2; ++mi)
#pragma unroll
        for (int ni = 0; ni < NF; ++ni)
#pragma unroll
            for (int c = 0; c < 4; ++c) acc[mi][ni][c] = 0.f;

    const float4* __restrict__ X4 = reinterpret_cast<const float4*>(X);
    const float4* __restrict__ W4 = reinterpret_cast<const float4*>(W);
    constexpr int KD4 = KDIM / 4;

    // Per-thread tile coordinates (invariant across k-steps)
    const int am = tid >> 1;                 // A: row pair layout: idx = tid + t*256
    float4 xreg[4], wreg[NBT];

    // Prologue: load first tiles into registers
    {
#pragma unroll
        for (int t = 0; t < 4; ++t) {
            int idx = tid + t * 256;
            int m = idx >> 3, kq = idx & 7;
            int r = row0 + m;
            xreg[t] = make_float4(0.f, 0.f, 0.f, 0.f);
            if (r < NN) xreg[t] = X4[(size_t)r * KD4 + kq];
        }
#pragma unroll
        for (int t = 0; t < NBT; ++t) {
            int idx = tid + t * 256;
            if (idx < BN * 8) {
                int f = idx >> 3, kq = idx & 7;
                wreg[t] = W4[(size_t)f * KD4 + kq];
            }
        }
    }
    (void)am;

    for (int k0 = 0; k0 < KDIM; k0 += BK) {
        // Store staged registers to SMEM (with tf32 rounding)
#pragma unroll
        for (int t = 0; t < 4; ++t) {
            int idx = tid + t * 256;
            int m = idx >> 3, kq = idx & 7;
            As[kq * 4 + 0][m] = f2tf32(xreg[t].x);
            As[kq * 4 + 1][m] = f2tf32(xreg[t].y);
            As[kq * 4 + 2][m] = f2tf32(xreg[t].z);
            As[kq * 4 + 3][m] = f2tf32(xreg[t].w);
        }
#pragma unroll
        for (int t = 0; t < NBT; ++t) {
            int idx = tid + t * 256;
            if (idx < BN * 8) {
                int f = idx >> 3, kq = idx & 7;
                Bs[kq * 4 + 0][f] = f2tf32(wreg[t].x);
                Bs[kq * 4 + 1][f] = f2tf32(wreg[t].y);
                Bs[kq * 4 + 2][f] = f2tf32(wreg[t].z);
                Bs[kq * 4 + 3][f] = f2tf32(wreg[t].w);
            }
        }
        __syncthreads();

        // Stage NEXT tiles (loads overlap the MMA loop below)
        int k1 = k0 + BK;
        if (k1 < KDIM) {
            int kb4 = k1 >> 2;
#pragma unroll
            for (int t = 0; t < 4; ++t) {
                int idx = tid + t * 256;
                int m = idx >> 3, kq = idx & 7;
                int r = row0 + m;
                xreg[t] = make_float4(0.f, 0.f, 0.f, 0.f);
                if (r < NN) xreg[t] = X4[(size_t)r * KD4 + kb4 + kq];
            }
#pragma unroll
            for (int t = 0; t < NBT; ++t) {
                int idx = tid + t * 256;
                if (idx < BN * 8) {
                    int f = idx >> 3, kq = idx & 7;
                    wreg[t] = W4[(size_t)f * KD4 + kb4 + kq];
                }
            }
        }

#pragma unroll
        for (int kf = 0; kf < BK / 8; ++kf) {
            int kb = kf * 8;
            uint32_t a[2][4];
#pragma unroll
            for (int mi = 0; mi < 2; ++mi) {
                int mb = m0 + mi * 16;
                a[mi][0] = __float_as_uint(As[kb + tig][mb + g]);
                a[mi][1] = __float_as_uint(As[kb + tig][mb + g + 8]);
                a[mi][2] = __float_as_uint(As[kb + tig + 4][mb + g]);
                a[mi][3] = __float_as_uint(As[kb + tig + 4][mb + g + 8]);
            }
            uint32_t b[NF][2];
#pragma unroll
            for (int ni = 0; ni < NF; ++ni) {
                int nb = n0 + ni * 8;
                b[ni][0] = __float_as_uint(Bs[kb + tig][nb + g]);
                b[ni][1] = __float_as_uint(Bs[kb + tig + 4][nb + g]);
            }
#pragma unroll
            for (int mi = 0; mi < 2; ++mi)
#pragma unroll
                for (int ni = 0; ni < NF; ++ni) {
                    asm volatile(
                        "mma.sync.aligned.m16n8k8.row.col.f32.tf32.tf32.f32 "
                        "{%0,%1,%2,%3},{%4,%5,%6,%7},{%8,%9},{%0,%1,%2,%3};"
                        : "+f"(acc[mi][ni][0]), "+f"(acc[mi][ni][1]),
                          "+f"(acc[mi][ni][2]), "+f"(acc[mi][ni][3])
                        : "r"(a[mi][0]), "r"(a[mi][1]), "r"(a[mi][2]), "r"(a[mi][3]),
                          "r"(b[ni][0]), "r"(b[ni][1]));
                }
        }
        __syncthreads();
    }

#pragma unroll
    for (int mi = 0; mi < 2; ++mi) {
        int r0 = row0 + m0 + mi * 16 + g;
        int r1 = r0 + 8;
#pragma unroll
        for (int ni = 0; ni < NF; ++ni) {
            int c = n0 + ni * 8 + tig * 2;
            if (r0 < NN) {
                float2 v = make_float2(acc[mi][ni][0], acc[mi][ni][1]);
                *reinterpret_cast<float2*>(&Y[(size_t)r0 * BN + c]) = v;
            }
            if (r1 < NN) {
                float2 v = make_float2(acc[mi][ni][2], acc[mi][ni][3]);
                *reinterpret_cast<float2*>(&Y[(size_t)r1 * BN + c]) = v;
            }
        }
    }
}

// ----------------------------------------------------------------------------
// CSR aggregation: one warp/node, lanes 0..F/4-1 hold a float4 chunk.
// Dual accumulators for ILP. 512-thread blocks (16 warps).
// ----------------------------------------------------------------------------
template <int F, bool RELU, bool TO_H, int LAYER>
__global__ void aggregate(float* __restrict__ outExt) {
    constexpr int LANES = F / 4;
    int warp = blockIdx.x * (blockDim.x >> 5) + (threadIdx.x >> 5);
    if (warp >= NN) return;
    int lane = threadIdx.x & 31;
    const float4* __restrict__ xw4 = reinterpret_cast<const float4*>(g_xw);
    float* __restrict__ out = TO_H ? (float*)g_h : outExt;
    bool active = lane < LANES;

    float4 acc0 = make_float4(0.f, 0.f, 0.f, 0.f);
    float4 acc1 = make_float4(0.f, 0.f, 0.f, 0.f);
    int s = g_rowptr[warp], t = g_rowptr[warp + 1];
    for (int base = s; base < t; base += 32) {
        int idx = base + lane;
        int src = 0; float nrm = 0.f;
        if (idx < t) { src = g_src[idx]; nrm = g_norm[idx]; }
        int cnt = min(32, t - base);
        int j = 0;
        for (; j + 1 < cnt; j += 2) {
            int s0 = __shfl_sync(0xffffffffu, src, j);
            float n0 = __shfl_sync(0xffffffffu, nrm, j);
            int s1 = __shfl_sync(0xffffffffu, src, j + 1);
            float n1 = __shfl_sync(0xffffffffu, nrm, j + 1);
            if (active) {
                float4 v0 = xw4[(size_t)s0 * (F / 4) + lane];
                float4 v1 = xw4[(size_t)s1 * (F / 4) + lane];
                acc0.x += n0 * v0.x; acc0.y += n0 * v0.y;
                acc0.z += n0 * v0.z; acc0.w += n0 * v0.w;
                acc1.x += n1 * v1.x; acc1.y += n1 * v1.y;
                acc1.z += n1 * v1.z; acc1.w += n1 * v1.w;
            }
        }
        if (j < cnt) {
            int s0 = __shfl_sync(0xffffffffu, src, j);
            float n0 = __shfl_sync(0xffffffffu, nrm, j);
            if (active) {
                float4 v0 = xw4[(size_t)s0 * (F / 4) + lane];
                acc0.x += n0 * v0.x; acc0.y += n0 * v0.y;
                acc0.z += n0 * v0.z; acc0.w += n0 * v0.w;
            }
        }
    }
    float d = g_dis[warp];
    float sn = d * d;
    if (active) {
        float4 v = xw4[(size_t)warp * (F / 4) + lane];
        acc0.x += sn * v.x + acc1.x;
        acc0.y += sn * v.y + acc1.y;
        acc0.z += sn * v.z + acc1.z;
        acc0.w += sn * v.w + acc1.w;

        const float4* sc4 = reinterpret_cast<const float4*>(g_sc[LAYER]);
        const float4* sh4 = reinterpret_cast<const float4*>(g_sh[LAYER]);
        float4 sc = sc4[lane], sh = sh4[lane];
        float4 r;
        r.x = acc0.x * sc.x + sh.x;
        r.y = acc0.y * sc.y + sh.y;
        r.z = acc0.z * sc.z + sh.z;
        r.w = acc0.w * sc.w + sh.w;
        if (RELU) {
            r.x = fmaxf(r.x, 0.f); r.y = fmaxf(r.y, 0.f);
            r.z = fmaxf(r.z, 0.f); r.w = fmaxf(r.w, 0.f);
        }
        reinterpret_cast<float4*>(out)[(size_t)warp * (F / 4) + lane] = r;
    }
}

// ----------------------------------------------------------------------------
// Launch — 9 kernel launches, graph-capturable.
// ----------------------------------------------------------------------------
extern "C" void kernel_launch(void* const* d_in, const int* in_sizes, int n_in,
                              void* d_out, int out_size) {
    const float* x   = (const float*)d_in[0];
    const int*   ei  = (const int*)d_in[1];       // int32 (JAX x64 disabled)
    const float* ew  = (const float*)d_in[2];
    const float* W1  = (const float*)d_in[3];
    const float* b1  = (const float*)d_in[4];
    const float* W2  = (const float*)d_in[5];
    const float* b2  = (const float*)d_in[6];
    const float* W3  = (const float*)d_in[7];
    const float* b3  = (const float*)d_in[8];
    const float* g1  = (const float*)d_in[9];
    const float* be1 = (const float*)d_in[10];
    const float* m1  = (const float*)d_in[11];
    const float* v1  = (const float*)d_in[12];
    const float* g2  = (const float*)d_in[13];
    const float* be2 = (const float*)d_in[14];
    const float* m2  = (const float*)d_in[15];
    const float* v2  = (const float*)d_in[16];
    float* out = (float*)d_out;

    const int nbE = (EE + 255) / 256;   // 3125

    deg_count<<<nbE, 256>>>(ei, ew);
    scan_lookback<<<SCAN_NB, 1024>>>();
    fill_csr_affine<<<nbE + 3, 256>>>(ei, ew, nbE,
                                      g1, be1, m1, v1, b1,
                                      g2, be2, m2, v2, b2, b3);

    const int gemmBlocks = (NN + 127) / 128;   // 391
    const int aggBlocks  = (NN + 15) / 16;     // 16 warps/block of 512

    gemm_tc<FIN, FH, false><<<gemmBlocks, 256>>>(x, W1);
    aggregate<FH, true, true, 0><<<aggBlocks, 512>>>(nullptr);

    gemm_tc<FH, FH, true><<<gemmBlocks, 256>>>(nullptr, W2);
    aggregate<FH, true, true, 1><<<aggBlocks, 512>>>(nullptr);

    gemm_tc<FH, FOUT, true><<<gemmBlocks, 256>>>(nullptr, W3);
    aggregate<FOUT, false, false, 2><<<aggBlocks, 512>>>(out);
}